// round 2
// baseline (speedup 1.0000x reference)
#include <cuda_runtime.h>

#define T 4096
#define B 2048
#define NS 7
#define PRED 64

__constant__ float c_lrs[NS] = {0.01f, 0.08f, 0.1f, 0.15f, 0.2f, 0.25f, 1.0f};

// scratch (static device memory: allowed; no runtime allocation)
__device__ float g_delta[B];
__device__ float g_errs[B * NS];
__device__ float g_finals[B * NS];
__device__ int   g_src[B];
__device__ int   g_improve[B];
__device__ int   g_loc[B];
__device__ float g_filt[(size_t)B * T];

// ---------------------------------------------------------------------------
// K1: per-row delta = max - min
// ---------------------------------------------------------------------------
__global__ void delta_kernel(const float* __restrict__ data) {
    int b = blockIdx.x;
    const float4* row = (const float4*)(data + (size_t)b * T);
    float mn = INFINITY, mx = -INFINITY;
    for (int i = threadIdx.x; i < T / 4; i += blockDim.x) {
        float4 v = row[i];
        mn = fminf(mn, fminf(fminf(v.x, v.y), fminf(v.z, v.w)));
        mx = fmaxf(mx, fmaxf(fmaxf(v.x, v.y), fmaxf(v.z, v.w)));
    }
    __shared__ float smn[8], smx[8];
#pragma unroll
    for (int o = 16; o; o >>= 1) {
        mn = fminf(mn, __shfl_down_sync(0xffffffffu, mn, o));
        mx = fmaxf(mx, __shfl_down_sync(0xffffffffu, mx, o));
    }
    int w = threadIdx.x >> 5;
    if ((threadIdx.x & 31) == 0) { smn[w] = mn; smx[w] = mx; }
    __syncthreads();
    if (threadIdx.x == 0) {
        mn = smn[0]; mx = smx[0];
        for (int i = 1; i < (int)blockDim.x / 32; i++) {
            mn = fminf(mn, smn[i]); mx = fmaxf(mx, smx[i]);
        }
        g_delta[b] = mx - mn;
    }
}

// ---------------------------------------------------------------------------
// K2: one thread per (row, sigma). 8 lanes per row (lane 7 idle) so the
// warp's loads broadcast across sigma lanes and stay L1-resident.
// ---------------------------------------------------------------------------
__global__ void scan_kernel(const float* __restrict__ data) {
    int tid = blockIdx.x * blockDim.x + threadIdx.x;
    int b = tid >> 3;
    int s = tid & 7;
    if (b >= B || s >= NS) return;
    float sigma = c_lrs[s];
    float delta = g_delta[b];
    const float* row = data + (size_t)b * T;
    float level = row[0];
    float err = 0.0f;
#pragma unroll 8
    for (int t = 0; t < T; t++) {
        float y = __ldg(row + t);
        float d = y - level;                       // pred = level (pre-update)
        err = fmaf(d, d, err);
        float c = fminf(fmaxf(d, -delta), delta);
        level = fmaf(sigma, c, level);
    }
    g_errs[b * NS + s]   = err * (1.0f / (float)T);
    g_finals[b * NS + s] = level;
}

// ---------------------------------------------------------------------------
// K3: batch-sequential pick as parallel prefix scans. One block, 1024 threads.
//   rmin[b], loc[b]  = first-argmin over 7 sigmas
//   improve[b]       = rmin[b] < exclusive-prefix-min(rmin)
//   src[b]           = inclusive-prefix-max of (improve ? b : -1)
//   pr[b][:]         = finals[b][loc[src[b]]]
// ---------------------------------------------------------------------------
__global__ void pick_kernel(float* __restrict__ out_pr) {
    __shared__ float s_rmin[B];
    __shared__ int   s_loc[B];
    __shared__ float bufA[B];
    __shared__ float bufB[B];
    int tid = threadIdx.x;

#pragma unroll
    for (int k = 0; k < 2; k++) {
        int b = tid + k * 1024;
        float best = INFINITY; int bi = 0;
#pragma unroll
        for (int s = 0; s < NS; s++) {
            float e = g_errs[b * NS + s];
            if (e < best) { best = e; bi = s; }   // strict < -> first argmin
        }
        s_rmin[b] = best; s_loc[b] = bi; bufA[b] = best;
    }
    __syncthreads();

    // inclusive prefix-min over rmin (Hillis-Steele, ping-pong)
    float* in = bufA; float* out = bufB;
    for (int off = 1; off < B; off <<= 1) {
#pragma unroll
        for (int k = 0; k < 2; k++) {
            int b = tid + k * 1024;
            float v = in[b];
            if (b >= off) v = fminf(v, in[b - off]);
            out[b] = v;
        }
        __syncthreads();
        float* tmp = in; in = out; out = tmp;
    }
    // 'in' = inclusive prefix min; exclusive = in[b-1]
#pragma unroll
    for (int k = 0; k < 2; k++) {
        int b = tid + k * 1024;
        float epm = (b == 0) ? INFINITY : in[b - 1];
        int imp = (s_rmin[b] < epm) ? 1 : 0;
        g_improve[b] = imp;
        g_loc[b] = s_loc[b];
        out[b] = imp ? (float)b : -1.0f;   // src candidate into the spare buf
    }
    __syncthreads();

    // inclusive prefix-max of src candidates
    float* in2 = out; float* out2 = in;
    for (int off = 1; off < B; off <<= 1) {
#pragma unroll
        for (int k = 0; k < 2; k++) {
            int b = tid + k * 1024;
            float v = in2[b];
            if (b >= off) v = fmaxf(v, in2[b - off]);
            out2[b] = v;
        }
        __syncthreads();
        float* tmp = in2; in2 = out2; out2 = tmp;
    }

#pragma unroll
    for (int k = 0; k < 2; k++) {
        int b = tid + k * 1024;
        int src = (int)in2[b];
        g_src[b] = src;
        int sidx = s_loc[src];
        float pv = g_finals[b * NS + sidx];
        float* pr = out_pr + (size_t)b * PRED;
#pragma unroll
        for (int j = 0; j < PRED; j++) pr[j] = pv;
    }
}

// ---------------------------------------------------------------------------
// K4: recompute filtered series only for improving rows (prefix-min records,
// ~O(log B) of them), store to scratch.
// ---------------------------------------------------------------------------
__global__ void filt_kernel(const float* __restrict__ data) {
    int b = blockIdx.x * blockDim.x + threadIdx.x;
    if (b >= B) return;
    if (!g_improve[b]) return;
    float sigma = c_lrs[g_loc[b]];
    float delta = g_delta[b];
    const float* row = data + (size_t)b * T;
    float* frow = g_filt + (size_t)b * T;
    float level = row[0];
#pragma unroll 4
    for (int t = 0; t < T; t++) {
        frow[t] = level;                           // filt[t] = pre-update level
        float y = __ldg(row + t);
        float d = y - level;
        float c = fminf(fmaxf(d, -delta), delta);
        level = fmaf(sigma, c, level);
    }
}

// ---------------------------------------------------------------------------
// K5: out1[b][t] = data[b][t] - filt[src[b]][t], float4-vectorized
// ---------------------------------------------------------------------------
__global__ void out_kernel(const float* __restrict__ data, float* __restrict__ out1) {
    int idx = blockIdx.x * blockDim.x + threadIdx.x;   // over B*T/4
    int b = idx >> 10;                                  // T/4 = 1024 vec4 per row
    int off = idx & 1023;
    if (b >= B) return;
    int src = g_src[b];
    float4 dv = ((const float4*)(data + (size_t)b * T))[off];
    float4 fv = ((const float4*)(g_filt + (size_t)src * T))[off];
    float4 r;
    r.x = dv.x - fv.x; r.y = dv.y - fv.y; r.z = dv.z - fv.z; r.w = dv.w - fv.w;
    ((float4*)(out1 + (size_t)b * T))[off] = r;
}

// ---------------------------------------------------------------------------
extern "C" void kernel_launch(void* const* d_in, const int* in_sizes, int n_in,
                              void* d_out, int out_size) {
    const float* data = (const float*)d_in[0];
    float* out = (float*)d_out;
    float* out1 = out;                       // [B, T]  data - sm
    float* out_pr = out + (size_t)B * T;     // [B, 64] forecast

    delta_kernel<<<B, 256>>>(data);
    scan_kernel<<<(B * 8) / 256, 256>>>(data);
    pick_kernel<<<1, 1024>>>(out_pr);
    filt_kernel<<<B / 256, 256>>>(data);
    out_kernel<<<(B * (T / 4)) / 256, 256>>>(data, out1);
}

// round 3
// speedup vs baseline: 6.1613x; 6.1613x over previous
#include <cuda_runtime.h>

#define T 4096
#define B 2048
#define NS 7
#define PRED 64

__constant__ float c_lrs[NS] = {0.01f, 0.08f, 0.1f, 0.15f, 0.2f, 0.25f, 1.0f};

__device__ float g_errs[B * NS];
__device__ float g_finals[B * NS];
__device__ int   g_src[B];
__device__ int   g_improve[B];
__device__ int   g_loc[B];
__device__ float g_filt[(size_t)B * T];

// padded smem index: pad 1 float per 128 -> stride 129, conflict-free for
// lane-strided segment access (129 mod 32 = 1)
#define SIDX(i)  ((i) + ((i) >> 7))
#define SROW_SZ  (T + (T >> 7))       // 4128 floats

// padded index for 16-wide segments (stride 17, 17 odd -> conflict-free)
#define SIDX2(i) ((i) + ((i) >> 4))
#define SROW2_SZ (T + (T >> 4))       // 4352 floats

// ---------------------------------------------------------------------------
// K1: per-row, all 7 sigmas. The clip is a provable no-op (level stays a
// convex combination of row values, so |y-level| <= max-min = delta), so the
// recurrence is affine: L' = (1-s)L + s*y. Each warp handles one sigma via a
// 32-lane affine prefix scan (128-step segments, two passes).
// ---------------------------------------------------------------------------
__global__ __launch_bounds__(256) void scan_kernel(const float* __restrict__ data) {
    __shared__ float s_row[SROW_SZ];
    int b = blockIdx.x;
    const float* row = data + (size_t)b * T;
    for (int i = threadIdx.x; i < T; i += blockDim.x)
        s_row[SIDX(i)] = __ldg(row + i);
    __syncthreads();

    int w = threadIdx.x >> 5, lane = threadIdx.x & 31;
    if (w >= NS) return;
    float sigma = c_lrs[w];
    float a = 1.0f - sigma;
    float A = a;                       // a^128 by 7 squarings
#pragma unroll
    for (int i = 0; i < 7; i++) A *= A;

    const int SEG = T / 32;            // 128
    int base = lane * SEG;

    // pass 1: segment transform c (L_end = A*L_start + c)
    float c = 0.0f;
#pragma unroll 8
    for (int j = 0; j < SEG; j++)
        c = fmaf(a, c, sigma * s_row[SIDX(base + j)]);

    // inclusive scan composing (A,c), earlier lanes applied first
    float Ai = A, ci = c;
#pragma unroll
    for (int off = 1; off < 32; off <<= 1) {
        float Ap = __shfl_up_sync(0xffffffffu, Ai, off);
        float cp = __shfl_up_sync(0xffffffffu, ci, off);
        if (lane >= off) { ci = fmaf(Ai, cp, ci); Ai *= Ap; }
    }
    // exclusive = inclusive of lane-1, applied to L0 = y0
    float Ae = __shfl_up_sync(0xffffffffu, Ai, 1);
    float ce = __shfl_up_sync(0xffffffffu, ci, 1);
    float y0 = s_row[0];
    float L = (lane == 0) ? y0 : fmaf(Ae, y0, ce);

    // pass 2: exact recurrence from segment-start level, accumulate err
    float err = 0.0f;
#pragma unroll 8
    for (int j = 0; j < SEG; j++) {
        float y = s_row[SIDX(base + j)];
        float d = y - L;               // pred = pre-update level
        err = fmaf(d, d, err);
        L = fmaf(sigma, d, L);
    }
#pragma unroll
    for (int off = 16; off; off >>= 1)
        err += __shfl_down_sync(0xffffffffu, err, off);
    float Lfin = __shfl_sync(0xffffffffu, L, 31);
    if (lane == 0) {
        g_errs[b * NS + w]   = err * (1.0f / (float)T);
        g_finals[b * NS + w] = Lfin;
    }
}

// ---------------------------------------------------------------------------
// K2: batch-sequential pick as parallel prefix scans. One block, 1024 threads.
// ---------------------------------------------------------------------------
__global__ void pick_kernel(float* __restrict__ out_pr) {
    __shared__ float s_rmin[B];
    __shared__ int   s_loc[B];
    __shared__ float bufA[B];
    __shared__ float bufB[B];
    int tid = threadIdx.x;

#pragma unroll
    for (int k = 0; k < 2; k++) {
        int b = tid + k * 1024;
        float best = INFINITY; int bi = 0;
#pragma unroll
        for (int s = 0; s < NS; s++) {
            float e = g_errs[b * NS + s];
            if (e < best) { best = e; bi = s; }    // strict < -> first argmin
        }
        s_rmin[b] = best; s_loc[b] = bi; bufA[b] = best;
    }
    __syncthreads();

    float* in = bufA; float* out = bufB;
    for (int off = 1; off < B; off <<= 1) {
#pragma unroll
        for (int k = 0; k < 2; k++) {
            int b = tid + k * 1024;
            float v = in[b];
            if (b >= off) v = fminf(v, in[b - off]);
            out[b] = v;
        }
        __syncthreads();
        float* tmp = in; in = out; out = tmp;
    }
#pragma unroll
    for (int k = 0; k < 2; k++) {
        int b = tid + k * 1024;
        float epm = (b == 0) ? INFINITY : in[b - 1];
        int imp = (s_rmin[b] < epm) ? 1 : 0;
        g_improve[b] = imp;
        g_loc[b] = s_loc[b];
        out[b] = imp ? (float)b : -1.0f;
    }
    __syncthreads();

    float* in2 = out; float* out2 = in;
    for (int off = 1; off < B; off <<= 1) {
#pragma unroll
        for (int k = 0; k < 2; k++) {
            int b = tid + k * 1024;
            float v = in2[b];
            if (b >= off) v = fmaxf(v, in2[b - off]);
            out2[b] = v;
        }
        __syncthreads();
        float* tmp = in2; in2 = out2; out2 = tmp;
    }

#pragma unroll
    for (int k = 0; k < 2; k++) {
        int b = tid + k * 1024;
        int src = (int)in2[b];
        g_src[b] = src;
        float pv = g_finals[b * NS + s_loc[src]];
        float4 pv4 = make_float4(pv, pv, pv, pv);
        float4* pr = (float4*)(out_pr + (size_t)b * PRED);
#pragma unroll
        for (int j = 0; j < PRED / 4; j++) pr[j] = pv4;
    }
}

// ---------------------------------------------------------------------------
// K3: filt recompute only for improving rows (~O(log B)), block-parallel
// affine scan: 256 threads x 16-step segments. filt written via smem so the
// global store is coalesced.
// ---------------------------------------------------------------------------
__global__ __launch_bounds__(256) void filt_kernel(const float* __restrict__ data) {
    int b = blockIdx.x;
    if (!g_improve[b]) return;
    __shared__ float s_row[SROW2_SZ];
    __shared__ float sA[256], sC[256];

    float sigma = c_lrs[g_loc[b]];
    float a = 1.0f - sigma;
    const float* row = data + (size_t)b * T;
    float* frow = g_filt + (size_t)b * T;
    int t = threadIdx.x;

    for (int i = t; i < T; i += 256)
        s_row[SIDX2(i)] = __ldg(row + i);
    __syncthreads();

    const int SEG = T / 256;           // 16
    int base = t * SEG;
    float A = a;                       // a^16 by 4 squarings
#pragma unroll
    for (int i = 0; i < 4; i++) A *= A;

    float c = 0.0f;
#pragma unroll
    for (int j = 0; j < SEG; j++)
        c = fmaf(a, c, sigma * s_row[SIDX2(base + j)]);

    sA[t] = A; sC[t] = c;
    __syncthreads();
    float Ai = A, ci = c;
    for (int off = 1; off < 256; off <<= 1) {
        float Ap = 0.0f, cp = 0.0f;
        if (t >= off) { Ap = sA[t - off]; cp = sC[t - off]; }
        __syncthreads();
        if (t >= off) { ci = fmaf(Ai, cp, ci); Ai *= Ap; }
        sA[t] = Ai; sC[t] = ci;
        __syncthreads();
    }
    float y0 = s_row[0];
    float L = (t == 0) ? y0 : fmaf(sA[t - 1], y0, sC[t - 1]);
    __syncthreads();

    // pass 2: overwrite row in smem with filt values (read-then-write)
#pragma unroll
    for (int j = 0; j < SEG; j++) {
        int idx = SIDX2(base + j);
        float y = s_row[idx];
        s_row[idx] = L;                // filt[t] = pre-update level
        float d = y - L;
        L = fmaf(sigma, d, L);
    }
    __syncthreads();
    for (int i = t; i < T; i += 256)
        frow[i] = s_row[SIDX2(i)];
}

// ---------------------------------------------------------------------------
// K4: out1[b][t] = data[b][t] - filt[src[b]][t], float4-vectorized
// ---------------------------------------------------------------------------
__global__ void out_kernel(const float* __restrict__ data, float* __restrict__ out1) {
    int idx = blockIdx.x * blockDim.x + threadIdx.x;
    int b = idx >> 10;
    int off = idx & 1023;
    if (b >= B) return;
    int src = g_src[b];
    float4 dv = ((const float4*)(data + (size_t)b * T))[off];
    float4 fv = ((const float4*)(g_filt + (size_t)src * T))[off];
    float4 r;
    r.x = dv.x - fv.x; r.y = dv.y - fv.y; r.z = dv.z - fv.z; r.w = dv.w - fv.w;
    ((float4*)(out1 + (size_t)b * T))[off] = r;
}

// ---------------------------------------------------------------------------
extern "C" void kernel_launch(void* const* d_in, const int* in_sizes, int n_in,
                              void* d_out, int out_size) {
    const float* data = (const float*)d_in[0];
    float* out = (float*)d_out;
    float* out1 = out;                       // [B, T]  data - sm
    float* out_pr = out + (size_t)B * T;     // [B, 64] forecast

    scan_kernel<<<B, 256>>>(data);
    pick_kernel<<<1, 1024>>>(out_pr);
    filt_kernel<<<B, 256>>>(data);
    out_kernel<<<(B * (T / 4)) / 256, 256>>>(data, out1);
}

// round 4
// speedup vs baseline: 8.2095x; 1.3324x over previous
#include <cuda_runtime.h>

#define T 4096
#define B 2048
#define NS 7
#define PRED 64

__constant__ float c_lrs[NS] = {0.01f, 0.08f, 0.1f, 0.15f, 0.2f, 0.25f, 1.0f};

__device__ float g_errs[B * NS];
__device__ float g_finals[B * NS];
__device__ int   g_src[B];
__device__ int   g_sloc[B];      // sigma index of the source (record) row

// padded smem index: pad 1 float per 128 -> stride 129, conflict-free for
// lane-strided segment access (129 mod 32 = 1)
#define SIDX(i)  ((i) + ((i) >> 7))
#define SROW_SZ  (T + (T >> 7))       // 4128 floats

// padded index for 16-wide segments (stride 17, odd -> conflict-free)
#define SIDX2(i) ((i) + ((i) >> 4))
#define SROW2_SZ (T + (T >> 4))       // 4352 floats

// ---------------------------------------------------------------------------
// K1: per-row, all 7 sigmas. Clip is a provable no-op (level is a convex
// combination of row values, so |y-level| <= max-min = delta) -> affine
// recurrence L' = (1-s)L + s*y. One warp per sigma, 32-lane affine prefix
// scan over 128-step segments, two passes (pass 2 exact from seg starts).
// ---------------------------------------------------------------------------
__global__ __launch_bounds__(256) void scan_kernel(const float* __restrict__ data) {
    __shared__ float s_row[SROW_SZ];
    int b = blockIdx.x;
    const float* row = data + (size_t)b * T;
    for (int i = threadIdx.x; i < T; i += blockDim.x)
        s_row[SIDX(i)] = __ldg(row + i);
    __syncthreads();

    int w = threadIdx.x >> 5, lane = threadIdx.x & 31;
    if (w >= NS) return;
    float sigma = c_lrs[w];
    float a = 1.0f - sigma;
    float A = a;                       // a^128 by 7 squarings
#pragma unroll
    for (int i = 0; i < 7; i++) A *= A;

    const int SEG = T / 32;            // 128
    int base = lane * SEG;

    // pass 1: segment constant c (L_end = A*L_start + c)
    float c = 0.0f;
#pragma unroll 8
    for (int j = 0; j < SEG; j++)
        c = fmaf(a, c, sigma * s_row[SIDX(base + j)]);

    // inclusive shfl scan composing (A,c)
    float Ai = A, ci = c;
#pragma unroll
    for (int off = 1; off < 32; off <<= 1) {
        float Ap = __shfl_up_sync(0xffffffffu, Ai, off);
        float cp = __shfl_up_sync(0xffffffffu, ci, off);
        if (lane >= off) { ci = fmaf(Ai, cp, ci); Ai *= Ap; }
    }
    float Ae = __shfl_up_sync(0xffffffffu, Ai, 1);
    float ce = __shfl_up_sync(0xffffffffu, ci, 1);
    float y0 = s_row[0];
    float L = (lane == 0) ? y0 : fmaf(Ae, y0, ce);

    // pass 2: exact recurrence from segment-start level, accumulate err
    float err = 0.0f;
#pragma unroll 8
    for (int j = 0; j < SEG; j++) {
        float y = s_row[SIDX(base + j)];
        float d = y - L;               // pred = pre-update level
        err = fmaf(d, d, err);
        L = fmaf(sigma, d, L);
    }
#pragma unroll
    for (int off = 16; off; off >>= 1)
        err += __shfl_down_sync(0xffffffffu, err, off);
    float Lfin = __shfl_sync(0xffffffffu, L, 31);
    if (lane == 0) {
        g_errs[b * NS + w]   = err * (1.0f / (float)T);
        g_finals[b * NS + w] = Lfin;
    }
}

// ---------------------------------------------------------------------------
// K2: batch-sequential pick as parallel prefix scans. Writes only g_src /
// g_sloc (pred writes moved into K3 so they spread across 2048 blocks).
// ---------------------------------------------------------------------------
__global__ void pick_kernel() {
    __shared__ float s_rmin[B];
    __shared__ int   s_loc[B];
    __shared__ float bufA[B];
    __shared__ float bufB[B];
    int tid = threadIdx.x;

#pragma unroll
    for (int k = 0; k < 2; k++) {
        int b = tid + k * 1024;
        float best = INFINITY; int bi = 0;
#pragma unroll
        for (int s = 0; s < NS; s++) {
            float e = g_errs[b * NS + s];
            if (e < best) { best = e; bi = s; }    // strict < -> first argmin
        }
        s_rmin[b] = best; s_loc[b] = bi; bufA[b] = best;
    }
    __syncthreads();

    // inclusive prefix-min over row minima
    float* in = bufA; float* out = bufB;
    for (int off = 1; off < B; off <<= 1) {
#pragma unroll
        for (int k = 0; k < 2; k++) {
            int b = tid + k * 1024;
            float v = in[b];
            if (b >= off) v = fminf(v, in[b - off]);
            out[b] = v;
        }
        __syncthreads();
        float* tmp = in; in = out; out = tmp;
    }
#pragma unroll
    for (int k = 0; k < 2; k++) {
        int b = tid + k * 1024;
        float epm = (b == 0) ? INFINITY : in[b - 1];
        int imp = (s_rmin[b] < epm) ? 1 : 0;
        out[b] = imp ? (float)b : -1.0f;
    }
    __syncthreads();

    // inclusive prefix-max of improving indices -> src row per b
    float* in2 = out; float* out2 = in;
    for (int off = 1; off < B; off <<= 1) {
#pragma unroll
        for (int k = 0; k < 2; k++) {
            int b = tid + k * 1024;
            float v = in2[b];
            if (b >= off) v = fmaxf(v, in2[b - off]);
            out2[b] = v;
        }
        __syncthreads();
        float* tmp = in2; in2 = out2; out2 = tmp;
    }

#pragma unroll
    for (int k = 0; k < 2; k++) {
        int b = tid + k * 1024;
        int src = (int)in2[b];
        g_src[b]  = src;
        g_sloc[b] = s_loc[src];
    }
}

// ---------------------------------------------------------------------------
// K3 (fused filt + out + pr): block b recomputes filt of row src[b] via a
// 256-thread affine block scan (src rows are few and L2-hot), then writes
// out1[b] = data[b] - filt and the 64-wide flat forecast.
// ---------------------------------------------------------------------------
__global__ __launch_bounds__(256) void fused_out_kernel(
    const float* __restrict__ data, float* __restrict__ out1,
    float* __restrict__ out_pr) {
    __shared__ float s_row[SROW2_SZ];
    __shared__ float sA[256], sC[256];

    int b = blockIdx.x;
    int src  = g_src[b];
    int sloc = g_sloc[b];
    float sigma = c_lrs[sloc];
    float a = 1.0f - sigma;
    const float* srow = data + (size_t)src * T;
    int t = threadIdx.x;

    for (int i = t; i < T; i += 256)
        s_row[SIDX2(i)] = __ldg(srow + i);
    __syncthreads();

    const int SEG = T / 256;           // 16
    int base = t * SEG;
    float A = a;                       // a^16 by 4 squarings
#pragma unroll
    for (int i = 0; i < 4; i++) A *= A;

    float c = 0.0f;
#pragma unroll
    for (int j = 0; j < SEG; j++)
        c = fmaf(a, c, sigma * s_row[SIDX2(base + j)]);

    sA[t] = A; sC[t] = c;
    __syncthreads();
    float Ai = A, ci = c;
    for (int off = 1; off < 256; off <<= 1) {
        float Ap = 0.0f, cp = 0.0f;
        if (t >= off) { Ap = sA[t - off]; cp = sC[t - off]; }
        __syncthreads();
        if (t >= off) { ci = fmaf(Ai, cp, ci); Ai *= Ap; }
        sA[t] = Ai; sC[t] = ci;
        __syncthreads();
    }
    float y0 = s_row[0];
    float L = (t == 0) ? y0 : fmaf(sA[t - 1], y0, sC[t - 1]);
    __syncthreads();

    // pass 2: overwrite src row in smem with its filt values
#pragma unroll
    for (int j = 0; j < SEG; j++) {
        int idx = SIDX2(base + j);
        float y = s_row[idx];
        s_row[idx] = L;                // filt[t] = pre-update level
        float d = y - L;
        L = fmaf(sigma, d, L);
    }
    __syncthreads();

    // out1[b] = data[b] - filt (float4 global, scalar smem reads)
    const float4* drow = (const float4*)(data + (size_t)b * T);
    float4* orow = (float4*)(out1 + (size_t)b * T);
    for (int i = t; i < T / 4; i += 256) {
        float4 dv = __ldg(drow + i);
        int j = i * 4;
        float4 r;
        r.x = dv.x - s_row[SIDX2(j)];
        r.y = dv.y - s_row[SIDX2(j + 1)];
        r.z = dv.z - s_row[SIDX2(j + 2)];
        r.w = dv.w - s_row[SIDX2(j + 3)];
        orow[i] = r;
    }

    // 64-wide flat forecast for this row
    if (t < PRED / 4) {
        float pv = g_finals[b * NS + sloc];
        ((float4*)(out_pr + (size_t)b * PRED))[t] = make_float4(pv, pv, pv, pv);
    }
}

// ---------------------------------------------------------------------------
extern "C" void kernel_launch(void* const* d_in, const int* in_sizes, int n_in,
                              void* d_out, int out_size) {
    const float* data = (const float*)d_in[0];
    float* out = (float*)d_out;
    float* out1 = out;                       // [B, T]  data - sm
    float* out_pr = out + (size_t)B * T;     // [B, 64] forecast

    scan_kernel<<<B, 256>>>(data);
    pick_kernel<<<1, 1024>>>();
    fused_out_kernel<<<B, 256>>>(data, out1, out_pr);
}